// round 6
// baseline (speedup 1.0000x reference)
#include <cuda_runtime.h>
#include <cuda_fp16.h>
#include <math.h>

#define BATCH   1024
#define N_IN    1024
#define NLAYERS 5
#define NPL     2048
#define FANIN   16
#define N_OUT   256
// Layer 4 only reads rows < N_IN + 4*NPL = 9216; its outputs go straight to d_out.
#define W_ROWS  (N_IN + 4 * NPL)   // 9216
#define ROW_BYTES (BATCH * 2)

// Transposed fp16 value buffer: valsT[row, batch]. 18.9 MB, L2-resident.
__device__ __half g_vals[(size_t)W_ROWS * BATCH];
// Per-row liveness flag (1 = some live consumer reads this row).
__device__ unsigned char g_live[W_ROWS];

__device__ __forceinline__ float tanh_approx(float x) {
    float y;
    asm("tanh.approx.f32 %0, %1;" : "=f"(y) : "f"(x));
    return y;
}

// ---------------------------------------------------------------------------
// Liveness kernels (run each launch; edge_src is fixed input, work is tiny).
// ---------------------------------------------------------------------------
__global__ void live_clear_kernel() {
    int i = blockIdx.x * blockDim.x + threadIdx.x;
    if (i < W_ROWS) g_live[i] = 0;
}

// Mark sources of the final N_OUT nodes of layer 4.
__global__ void live_mark_final_kernel(const int* __restrict__ src_l4) {
    int j = blockIdx.x * blockDim.x + threadIdx.x;   // 0..N_OUT-1
    if (j >= N_OUT) return;
    const int n = NPL - N_OUT + j;
    const int* s = src_l4 + n * FANIN;
#pragma unroll
    for (int f = 0; f < FANIN; f++) g_live[s[f]] = 1;
}

// For hidden layer l (3,2,1): if node's row is live, mark its sources.
__global__ void live_backward_kernel(const int* __restrict__ src_l, int base_row) {
    int n = blockIdx.x * blockDim.x + threadIdx.x;   // 0..NPL-1
    if (n >= NPL) return;
    if (!g_live[base_row + n]) return;
    const int* s = src_l + n * FANIN;
#pragma unroll
    for (int f = 0; f < FANIN; f++) g_live[s[f]] = 1;
}

// ---------------------------------------------------------------------------
// Transpose + convert inputs [B, N_IN] f32 -> g_vals[N_IN, B] f16
// ---------------------------------------------------------------------------
__global__ void transpose_in_kernel(const float* __restrict__ in) {
    __shared__ float tile[32][33];
    int bx = blockIdx.x * 32;  // column tile
    int by = blockIdx.y * 32;  // batch tile
    int tx = threadIdx.x, ty = threadIdx.y;

    int x = bx + tx;
#pragma unroll
    for (int j = 0; j < 32; j += 8) {
        int y = by + ty + j;
        tile[ty + j][tx] = in[(size_t)y * N_IN + x];
    }
    __syncthreads();

    int xo = by + tx;
#pragma unroll
    for (int j = 0; j < 32; j += 8) {
        int yo = bx + ty + j;
        g_vals[(size_t)yo * BATCH + xo] = __float2half_rn(tile[tx][ty + j]);
    }
}

// ---------------------------------------------------------------------------
// One hidden layer. Block = 2 nodes x 128 threads; 8 batch elems/thread
// (one LDG.128 per fanin). Dead nodes exit immediately (liveness pruning).
// ---------------------------------------------------------------------------
__global__ void __launch_bounds__(256) layer_kernel(
    const int*   __restrict__ src,     // [NPL, FANIN]
    const float* __restrict__ wgt,     // [NPL, FANIN]
    const float* __restrict__ bias,    // [NPL]
    int out_base_row)                  // N_IN + l*NPL
{
    const int n = blockIdx.x * 2 + (threadIdx.x >> 7);
    const int t = threadIdx.x & 127;       // owns batch [t*8, t*8+8)

    const int row = out_base_row + n;
    if (!g_live[row]) return;              // dead node: skip all gathers + store

    int   sidx[FANIN];
    float wv[FANIN];
    {
        const int4*   s4 = (const int4*)(src + n * FANIN);
        const float4* w4 = (const float4*)(wgt + n * FANIN);
#pragma unroll
        for (int q = 0; q < FANIN / 4; q++) {
            int4   si = __ldg(s4 + q);
            float4 wi = __ldg(w4 + q);
            sidx[q*4+0] = si.x; sidx[q*4+1] = si.y;
            sidx[q*4+2] = si.z; sidx[q*4+3] = si.w;
            wv[q*4+0] = wi.x; wv[q*4+1] = wi.y;
            wv[q*4+2] = wi.z; wv[q*4+3] = wi.w;
        }
    }

    float bv = __ldg(bias + n);
    float acc[8];
#pragma unroll
    for (int i = 0; i < 8; i++) acc[i] = bv;

    const char* gbase = (const char*)g_vals;
    const unsigned toff = (unsigned)t * 16u;
#pragma unroll
    for (int f = 0; f < FANIN; f++) {
        uint4 v = *(const uint4*)(gbase + (unsigned)sidx[f] * (unsigned)ROW_BYTES + toff);
        float wf = wv[f];
        float2 f0 = __half22float2(*(__half2*)&v.x);
        float2 f1 = __half22float2(*(__half2*)&v.y);
        float2 f2 = __half22float2(*(__half2*)&v.z);
        float2 f3 = __half22float2(*(__half2*)&v.w);
        acc[0] = fmaf(wf, f0.x, acc[0]);
        acc[1] = fmaf(wf, f0.y, acc[1]);
        acc[2] = fmaf(wf, f1.x, acc[2]);
        acc[3] = fmaf(wf, f1.y, acc[3]);
        acc[4] = fmaf(wf, f2.x, acc[4]);
        acc[5] = fmaf(wf, f2.y, acc[5]);
        acc[6] = fmaf(wf, f3.x, acc[6]);
        acc[7] = fmaf(wf, f3.y, acc[7]);
    }

#pragma unroll
    for (int i = 0; i < 8; i++) acc[i] = tanh_approx(acc[i]);

    uint4 o;
    *(__half2*)&o.x = __floats2half2_rn(acc[0], acc[1]);
    *(__half2*)&o.y = __floats2half2_rn(acc[2], acc[3]);
    *(__half2*)&o.z = __floats2half2_rn(acc[4], acc[5]);
    *(__half2*)&o.w = __floats2half2_rn(acc[6], acc[7]);
    *(uint4*)&g_vals[(size_t)row * BATCH + t * 8] = o;
}

// ---------------------------------------------------------------------------
// Final layer: last N_OUT nodes, accurate sigmoid, f32 out [B, N_OUT].
// ---------------------------------------------------------------------------
__global__ void __launch_bounds__(256) final_layer_kernel(
    const int*   __restrict__ src,     // layer-4 [NPL, FANIN]
    const float* __restrict__ wgt,
    const float* __restrict__ bias,
    float*       __restrict__ out)
{
    const int j = blockIdx.x * 2 + (threadIdx.x >> 7);  // 0..N_OUT-1
    const int n = NPL - N_OUT + j;
    const int t = threadIdx.x & 127;

    int   sidx[FANIN];
    float wv[FANIN];
    {
        const int4*   s4 = (const int4*)(src + n * FANIN);
        const float4* w4 = (const float4*)(wgt + n * FANIN);
#pragma unroll
        for (int q = 0; q < FANIN / 4; q++) {
            int4   si = __ldg(s4 + q);
            float4 wi = __ldg(w4 + q);
            sidx[q*4+0] = si.x; sidx[q*4+1] = si.y;
            sidx[q*4+2] = si.z; sidx[q*4+3] = si.w;
            wv[q*4+0] = wi.x; wv[q*4+1] = wi.y;
            wv[q*4+2] = wi.z; wv[q*4+3] = wi.w;
        }
    }

    float bv = __ldg(bias + n);
    float acc[8];
#pragma unroll
    for (int i = 0; i < 8; i++) acc[i] = bv;

    const char* gbase = (const char*)g_vals;
    const unsigned toff = (unsigned)t * 16u;
#pragma unroll
    for (int f = 0; f < FANIN; f++) {
        uint4 v = *(const uint4*)(gbase + (unsigned)sidx[f] * (unsigned)ROW_BYTES + toff);
        float wf = wv[f];
        float2 f0 = __half22float2(*(__half2*)&v.x);
        float2 f1 = __half22float2(*(__half2*)&v.y);
        float2 f2 = __half22float2(*(__half2*)&v.z);
        float2 f3 = __half22float2(*(__half2*)&v.w);
        acc[0] = fmaf(wf, f0.x, acc[0]);
        acc[1] = fmaf(wf, f0.y, acc[1]);
        acc[2] = fmaf(wf, f1.x, acc[2]);
        acc[3] = fmaf(wf, f1.y, acc[3]);
        acc[4] = fmaf(wf, f2.x, acc[4]);
        acc[5] = fmaf(wf, f2.y, acc[5]);
        acc[6] = fmaf(wf, f3.x, acc[6]);
        acc[7] = fmaf(wf, f3.y, acc[7]);
    }

    const int b = t * 8;
#pragma unroll
    for (int i = 0; i < 8; i++) {
        float s = 1.0f / (1.0f + expf(-acc[i]));
        out[(size_t)(b + i) * N_OUT + j] = s;
    }
}

// ---------------------------------------------------------------------------
extern "C" void kernel_launch(void* const* d_in, const int* in_sizes, int n_in,
                              void* d_out, int out_size) {
    const float* inputs   = (const float*)d_in[0];   // [B, N_IN]
    const int*   edge_src = (const int*)  d_in[1];   // [L, NPL, FANIN]
    const float* edge_w   = (const float*)d_in[2];   // [L, NPL, FANIN]
    const float* biases   = (const float*)d_in[3];   // [L, NPL]
    float*       out      = (float*)d_out;

    // --- liveness backward pass (tiny; overlaps nothing it shouldn't) ---
    live_clear_kernel<<<(W_ROWS + 255) / 256, 256>>>();
    live_mark_final_kernel<<<1, 256>>>(edge_src + (size_t)4 * NPL * FANIN);
    for (int l = 3; l >= 1; l--) {
        live_backward_kernel<<<NPL / 256, 256>>>(
            edge_src + (size_t)l * NPL * FANIN, N_IN + l * NPL);
    }

    // --- forward ---
    transpose_in_kernel<<<dim3(N_IN / 32, BATCH / 32), dim3(32, 8)>>>(inputs);

    for (int l = 0; l < NLAYERS - 1; l++) {
        layer_kernel<<<NPL / 2, 256>>>(
            edge_src + (size_t)l * NPL * FANIN,
            edge_w   + (size_t)l * NPL * FANIN,
            biases   + (size_t)l * NPL,
            N_IN + l * NPL);
    }

    final_layer_kernel<<<N_OUT / 2, 256>>>(
        edge_src + (size_t)4 * NPL * FANIN,
        edge_w   + (size_t)4 * NPL * FANIN,
        biases   + (size_t)4 * NPL,
        out);
}

// round 7
// speedup vs baseline: 1.3951x; 1.3951x over previous
#include <cuda_runtime.h>
#include <cuda_fp16.h>
#include <math.h>

#define BATCH   1024
#define N_IN    1024
#define NLAYERS 5
#define NPL     2048
#define FANIN   16
#define N_OUT   256
#define W_ROWS  (N_IN + 4 * NPL)   // 9216
#define ROW_BYTES (BATCH * 2)
#define L2_BASE (N_IN + 2 * NPL)   // 5120
#define L3_BASE (N_IN + 3 * NPL)   // 7168

// Transposed fp16 value buffer: valsT[row, batch]. 18.9 MB, L2-resident.
__device__ __half g_vals[(size_t)W_ROWS * BATCH];
// Liveness bitmaps for layers 2 and 3 (bit n = node n of that layer).
__device__ unsigned g_liveL2[NPL / 32];
__device__ unsigned g_liveL3[NPL / 32];

__device__ __forceinline__ float tanh_approx(float x) {
    float y;
    asm("tanh.approx.f32 %0, %1;" : "=f"(y) : "f"(x));
    return y;
}

// ---------------------------------------------------------------------------
// Single-block liveness: shared bitmaps, two phases, ~2us.
// ---------------------------------------------------------------------------
__global__ void __launch_bounds__(1024) liveness_kernel(
    const int* __restrict__ src_l3,   // layer-3 edge_src [NPL, FANIN]
    const int* __restrict__ src_l4)   // layer-4 edge_src [NPL, FANIN]
{
    __shared__ unsigned bmL3[NPL / 32];
    __shared__ unsigned bmL2[NPL / 32];
    const int t = threadIdx.x;

    if (t < NPL / 32) { bmL3[t] = 0u; bmL2[t] = 0u; }
    __syncthreads();

    // Phase 1: sources of the final N_OUT output nodes.
    if (t < N_OUT) {
        const int4* s4 = (const int4*)(src_l4 + (NPL - N_OUT + t) * FANIN);
#pragma unroll
        for (int q = 0; q < FANIN / 4; q++) {
            int4 si = __ldg(s4 + q);
            int v[4] = { si.x, si.y, si.z, si.w };
#pragma unroll
            for (int k = 0; k < 4; k++) {
                int idx = v[k];
                if (idx >= L3_BASE) {
                    int n = idx - L3_BASE;
                    atomicOr(&bmL3[n >> 5], 1u << (n & 31));
                } else if (idx >= L2_BASE) {
                    int n = idx - L2_BASE;
                    atomicOr(&bmL2[n >> 5], 1u << (n & 31));
                }
            }
        }
    }
    __syncthreads();

    // Phase 2: live layer-3 nodes mark their layer-2 sources.
#pragma unroll 1
    for (int n = t; n < NPL; n += 1024) {
        if ((bmL3[n >> 5] >> (n & 31)) & 1u) {
            const int4* s4 = (const int4*)(src_l3 + n * FANIN);
#pragma unroll
            for (int q = 0; q < FANIN / 4; q++) {
                int4 si = __ldg(s4 + q);
                int v[4] = { si.x, si.y, si.z, si.w };
#pragma unroll
                for (int k = 0; k < 4; k++) {
                    int idx = v[k];
                    if (idx >= L2_BASE) {   // layer-3 srcs are all < L3_BASE
                        int m = idx - L2_BASE;
                        atomicOr(&bmL2[m >> 5], 1u << (m & 31));
                    }
                }
            }
        }
    }
    __syncthreads();

    if (t < NPL / 32) { g_liveL3[t] = bmL3[t]; g_liveL2[t] = bmL2[t]; }
}

// ---------------------------------------------------------------------------
// Transpose + convert inputs [B, N_IN] f32 -> g_vals[N_IN, B] f16
// ---------------------------------------------------------------------------
__global__ void transpose_in_kernel(const float* __restrict__ in) {
    __shared__ float tile[32][33];
    int bx = blockIdx.x * 32;
    int by = blockIdx.y * 32;
    int tx = threadIdx.x, ty = threadIdx.y;

#pragma unroll
    for (int j = 0; j < 32; j += 8)
        tile[ty + j][tx] = in[(size_t)(by + ty + j) * N_IN + bx + tx];
    __syncthreads();
#pragma unroll
    for (int j = 0; j < 32; j += 8)
        g_vals[(size_t)(bx + ty + j) * BATCH + by + tx] =
            __float2half_rn(tile[tx][ty + j]);
}

// ---------------------------------------------------------------------------
// Hidden layer. Block = 2 nodes x 128 threads; 8 batch elems/thread.
// mode: 0 = no pruning, 2 = test g_liveL2, 3 = test g_liveL3.
// ---------------------------------------------------------------------------
__global__ void __launch_bounds__(256) layer_kernel(
    const int*   __restrict__ src,
    const float* __restrict__ wgt,
    const float* __restrict__ bias,
    int out_base_row, int mode)
{
    const int n = blockIdx.x * 2 + (threadIdx.x >> 7);
    const int t = threadIdx.x & 127;

    if (mode != 0) {
        const unsigned* lm = (mode == 3) ? g_liveL3 : g_liveL2;
        if (!((lm[n >> 5] >> (n & 31)) & 1u)) return;   // dead node
    }

    int   sidx[FANIN];
    float wv[FANIN];
    {
        const int4*   s4 = (const int4*)(src + n * FANIN);
        const float4* w4 = (const float4*)(wgt + n * FANIN);
#pragma unroll
        for (int q = 0; q < FANIN / 4; q++) {
            int4   si = __ldg(s4 + q);
            float4 wi = __ldg(w4 + q);
            sidx[q*4+0] = si.x; sidx[q*4+1] = si.y;
            sidx[q*4+2] = si.z; sidx[q*4+3] = si.w;
            wv[q*4+0] = wi.x; wv[q*4+1] = wi.y;
            wv[q*4+2] = wi.z; wv[q*4+3] = wi.w;
        }
    }

    float bv = __ldg(bias + n);
    float acc[8];
#pragma unroll
    for (int i = 0; i < 8; i++) acc[i] = bv;

    const char* gbase = (const char*)g_vals;
    const unsigned toff = (unsigned)t * 16u;
#pragma unroll
    for (int f = 0; f < FANIN; f++) {
        uint4 v = *(const uint4*)(gbase + (unsigned)sidx[f] * (unsigned)ROW_BYTES + toff);
        float wf = wv[f];
        float2 f0 = __half22float2(*(__half2*)&v.x);
        float2 f1 = __half22float2(*(__half2*)&v.y);
        float2 f2 = __half22float2(*(__half2*)&v.z);
        float2 f3 = __half22float2(*(__half2*)&v.w);
        acc[0] = fmaf(wf, f0.x, acc[0]);
        acc[1] = fmaf(wf, f0.y, acc[1]);
        acc[2] = fmaf(wf, f1.x, acc[2]);
        acc[3] = fmaf(wf, f1.y, acc[3]);
        acc[4] = fmaf(wf, f2.x, acc[4]);
        acc[5] = fmaf(wf, f2.y, acc[5]);
        acc[6] = fmaf(wf, f3.x, acc[6]);
        acc[7] = fmaf(wf, f3.y, acc[7]);
    }

#pragma unroll
    for (int i = 0; i < 8; i++) acc[i] = tanh_approx(acc[i]);

    uint4 o;
    *(__half2*)&o.x = __floats2half2_rn(acc[0], acc[1]);
    *(__half2*)&o.y = __floats2half2_rn(acc[2], acc[3]);
    *(__half2*)&o.z = __floats2half2_rn(acc[4], acc[5]);
    *(__half2*)&o.w = __floats2half2_rn(acc[6], acc[7]);
    *(uint4*)&g_vals[(size_t)(out_base_row + n) * BATCH + t * 8] = o;
}

// ---------------------------------------------------------------------------
// Final layer: last N_OUT nodes, accurate sigmoid, f32 out [B, N_OUT].
// ---------------------------------------------------------------------------
__global__ void __launch_bounds__(256) final_layer_kernel(
    const int*   __restrict__ src,
    const float* __restrict__ wgt,
    const float* __restrict__ bias,
    float*       __restrict__ out)
{
    const int j = blockIdx.x * 2 + (threadIdx.x >> 7);
    const int n = NPL - N_OUT + j;
    const int t = threadIdx.x & 127;

    int   sidx[FANIN];
    float wv[FANIN];
    {
        const int4*   s4 = (const int4*)(src + n * FANIN);
        const float4* w4 = (const float4*)(wgt + n * FANIN);
#pragma unroll
        for (int q = 0; q < FANIN / 4; q++) {
            int4   si = __ldg(s4 + q);
            float4 wi = __ldg(w4 + q);
            sidx[q*4+0] = si.x; sidx[q*4+1] = si.y;
            sidx[q*4+2] = si.z; sidx[q*4+3] = si.w;
            wv[q*4+0] = wi.x; wv[q*4+1] = wi.y;
            wv[q*4+2] = wi.z; wv[q*4+3] = wi.w;
        }
    }

    float bv = __ldg(bias + n);
    float acc[8];
#pragma unroll
    for (int i = 0; i < 8; i++) acc[i] = bv;

    const char* gbase = (const char*)g_vals;
    const unsigned toff = (unsigned)t * 16u;
#pragma unroll
    for (int f = 0; f < FANIN; f++) {
        uint4 v = *(const uint4*)(gbase + (unsigned)sidx[f] * (unsigned)ROW_BYTES + toff);
        float wf = wv[f];
        float2 f0 = __half22float2(*(__half2*)&v.x);
        float2 f1 = __half22float2(*(__half2*)&v.y);
        float2 f2 = __half22float2(*(__half2*)&v.z);
        float2 f3 = __half22float2(*(__half2*)&v.w);
        acc[0] = fmaf(wf, f0.x, acc[0]);
        acc[1] = fmaf(wf, f0.y, acc[1]);
        acc[2] = fmaf(wf, f1.x, acc[2]);
        acc[3] = fmaf(wf, f1.y, acc[3]);
        acc[4] = fmaf(wf, f2.x, acc[4]);
        acc[5] = fmaf(wf, f2.y, acc[5]);
        acc[6] = fmaf(wf, f3.x, acc[6]);
        acc[7] = fmaf(wf, f3.y, acc[7]);
    }

    const int b = t * 8;
#pragma unroll
    for (int i = 0; i < 8; i++) {
        float s = 1.0f / (1.0f + expf(-acc[i]));
        out[(size_t)(b + i) * N_OUT + j] = s;
    }
}

// ---------------------------------------------------------------------------
extern "C" void kernel_launch(void* const* d_in, const int* in_sizes, int n_in,
                              void* d_out, int out_size) {
    const float* inputs   = (const float*)d_in[0];   // [B, N_IN]
    const int*   edge_src = (const int*)  d_in[1];   // [L, NPL, FANIN]
    const float* edge_w   = (const float*)d_in[2];   // [L, NPL, FANIN]
    const float* biases   = (const float*)d_in[3];   // [L, NPL]
    float*       out      = (float*)d_out;

    // Cheap single-block liveness (L2 + L3 bitmaps).
    liveness_kernel<<<1, 1024>>>(
        edge_src + (size_t)3 * NPL * FANIN,
        edge_src + (size_t)4 * NPL * FANIN);

    transpose_in_kernel<<<dim3(N_IN / 32, BATCH / 32), dim3(32, 8)>>>(inputs);

    for (int l = 0; l < NLAYERS - 1; l++) {
        int mode = (l == 2) ? 2 : (l == 3) ? 3 : 0;
        layer_kernel<<<NPL / 2, 256>>>(
            edge_src + (size_t)l * NPL * FANIN,
            edge_w   + (size_t)l * NPL * FANIN,
            biases   + (size_t)l * NPL,
            N_IN + l * NPL, mode);
    }

    final_layer_kernel<<<N_OUT / 2, 256>>>(
        edge_src + (size_t)4 * NPL * FANIN,
        edge_w   + (size_t)4 * NPL * FANIN,
        biases   + (size_t)4 * NPL,
        out);
}